// round 6
// baseline (speedup 1.0000x reference)
#include <cuda_runtime.h>

// Fixed shapes
#define NB      64
#define T_LEN   2048
#define DDIM    80
#define N_ROWS  (NB * T_LEN)          // 131072
#define N_ELEM  (N_ROWS * DDIM)       // 10,485,760
#define VPR     (DDIM / 4)            // 20 float4 per row

#define BX      20                    // one thread per float4 slot (no div!)
#define BY      16                    // rows per block
#define NTHREADS (BX * BY)            // 320
#define NWARPS  (NTHREADS / 32)       // 10
#define GBLOCKS (N_ROWS / BY)         // 8192

// Scratch (no device allocation allowed)
__device__ float        g_pc[GBLOCKS];
__device__ float        g_pl[GBLOCKS];
__device__ unsigned int g_count = 0;
__device__ __align__(16) float g_zero[DDIM];   // zero-initialized row

__device__ __forceinline__ float ex2f(float x) {
    float y; asm("ex2.approx.f32 %0, %1;" : "=f"(y) : "f"(x)); return y;
}
__device__ __forceinline__ float lg2f(float x) {
    float y; asm("lg2.approx.f32 %0, %1;" : "=f"(y) : "f"(x)); return y;
}

// One element: 9 shifted abs-diffs -> softmin partials (round-1 proven form)
__device__ __forceinline__ void elem(float xv,
                                     float u0, float u1, float u2,
                                     float m0, float m1, float m2,
                                     float b0, float b1, float b2,
                                     float& accC, float& accL)
{
    const float C = -46.166241308446828f;   // -32 * log2(e)
    float dc = xv - m1;                     // center (unshifted) diff
    float e0 = ex2f(C * fabsf(xv - u0));
    float e1 = ex2f(C * fabsf(xv - u1));
    float e2 = ex2f(C * fabsf(xv - u2));
    float e3 = ex2f(C * fabsf(xv - m0));
    float e4 = ex2f(C * fabsf(dc));
    float e5 = ex2f(C * fabsf(xv - m2));
    float e6 = ex2f(C * fabsf(xv - b0));
    float e7 = ex2f(C * fabsf(xv - b1));
    float e8 = ex2f(C * fabsf(xv - b2));
    float s = (((e0 + e1) + (e2 + e3)) + ((e4 + e5) + (e6 + e7))) + e8;
    accC += fabsf(dc);
    accL += lg2f(fmaxf(s, 1e-37f));
}

__global__ void __launch_bounds__(NTHREADS)
jitter_fused(const float* __restrict__ in, const float* __restrict__ tg,
             float* __restrict__ out)
{
    const int      jj  = threadIdx.x;                     // 0..19, no division
    const unsigned row = blockIdx.x * BY + threadIdx.y;   // < N_ROWS
    const unsigned i   = row & (T_LEN - 1);

    const float* rowM = tg + (size_t)row * DDIM;
    const float* rowU = (i > 0)         ? rowM - DDIM : g_zero;
    const float* rowD = (i < T_LEN - 1) ? rowM + DDIM : g_zero;

    const int base = jj * 4;
    const bool lv = (jj > 0);
    const bool rv = (jj < VPR - 1);

    float4 x4 = *reinterpret_cast<const float4*>(in + (size_t)row * DDIM + base);

    float4 u4 = *reinterpret_cast<const float4*>(rowU + base);
    float4 m4 = *reinterpret_cast<const float4*>(rowM + base);
    float4 b4 = *reinterpret_cast<const float4*>(rowD + base);

    float uL = lv ? rowU[base - 1] : 0.0f;
    float mL = lv ? rowM[base - 1] : 0.0f;
    float bL = lv ? rowD[base - 1] : 0.0f;
    float uR = rv ? rowU[base + 4] : 0.0f;
    float mR = rv ? rowM[base + 4] : 0.0f;
    float bR = rv ? rowD[base + 4] : 0.0f;

    float accC = 0.0f;
    float accL = 0.0f;

    elem(x4.x, uL,   u4.x, u4.y,  mL,   m4.x, m4.y,  bL,   b4.x, b4.y, accC, accL);
    elem(x4.y, u4.x, u4.y, u4.z,  m4.x, m4.y, m4.z,  b4.x, b4.y, b4.z, accC, accL);
    elem(x4.z, u4.y, u4.z, u4.w,  m4.y, m4.z, m4.w,  b4.y, b4.z, b4.w, accC, accL);
    elem(x4.w, u4.z, u4.w, uR,    m4.z, m4.w, mR,    b4.z, b4.w, bR,   accC, accL);

    // ---- deterministic in-block reduction: shuffle within warp, smem across
    const int tid  = threadIdx.y * BX + threadIdx.x;
    const int lane = tid & 31;
    const int wid  = tid >> 5;

    #pragma unroll
    for (int off = 16; off > 0; off >>= 1) {
        accC += __shfl_down_sync(0xFFFFFFFFu, accC, off);
        accL += __shfl_down_sync(0xFFFFFFFFu, accL, off);
    }

    __shared__ float shc[NWARPS];
    __shared__ float shl[NWARPS];
    if (lane == 0) { shc[wid] = accC; shl[wid] = accL; }
    __syncthreads();

    __shared__ bool isLast;
    if (tid == 0) {
        float sc = shc[0], sl = shl[0];
        #pragma unroll
        for (int w = 1; w < NWARPS; w++) { sc += shc[w]; sl += shl[w]; }
        g_pc[blockIdx.x] = sc;
        g_pl[blockIdx.x] = sl;
        __threadfence();
        unsigned ticket = atomicAdd(&g_count, 1u);
        isLast = (ticket == GBLOCKS - 1);
    }
    __syncthreads();

    if (isLast) {
        // last block: deterministic final sum over fixed index order
        double dc = 0.0, dl = 0.0;
        for (int k = tid; k < GBLOCKS; k += NTHREADS) {
            dc += (double)__ldcg(&g_pc[k]);
            dl += (double)__ldcg(&g_pl[k]);
        }
        // warp reduce doubles via shfl on hi/lo is messy; use smem tree
        __shared__ double dsc[NTHREADS];
        __shared__ double dsl[NTHREADS];
        dsc[tid] = dc; dsl[tid] = dl;
        __syncthreads();
        // 320 = 64*5: first fold 320 -> 64 (tid < 64 sums 5 strided slots)
        if (tid < 64) {
            double c = dsc[tid], l = dsl[tid];
            #pragma unroll
            for (int k = 1; k < 5; k++) { c += dsc[tid + 64 * k]; l += dsl[tid + 64 * k]; }
            dsc[tid] = c; dsl[tid] = l;
        }
        __syncthreads();
        #pragma unroll
        for (int off = 32; off > 0; off >>= 1) {
            if (tid < off) {
                dsc[tid] += dsc[tid + off];
                dsl[tid] += dsl[tid + off];
            }
            __syncthreads();
        }
        if (tid == 0) {
            const double Ad  = 46.166241308446828;   // 32*log2(e)
            const double C2d = -0.021660849392498291; // -ln(2)/32
            // accC was accumulated as |x - t| scaled? No: C-form keeps raw units.
            double res = (0.5 / (double)N_ELEM) * (dsc[0] + C2d * dsl[0]);
            (void)Ad;
            out[0] = (float)res;
            g_count = 0;   // reset ticket for graph replay
        }
    }
}

extern "C" void kernel_launch(void* const* d_in, const int* in_sizes, int n_in,
                              void* d_out, int out_size)
{
    const float* in = (const float*)d_in[0];
    const float* tg = (const float*)d_in[1];
    float* out = (float*)d_out;

    dim3 block(BX, BY);
    jitter_fused<<<GBLOCKS, block>>>(in, tg, out);
}

// round 7
// speedup vs baseline: 1.1239x; 1.1239x over previous
#include <cuda_runtime.h>

// Fixed shapes
#define NB      64
#define T_LEN   2048
#define DDIM    80
#define N_ROWS  (NB * T_LEN)          // 131072
#define N_ELEM  (N_ROWS * DDIM)       // 10,485,760
#define N_VEC   (N_ELEM / 4)          // 2,621,440 float4
#define VPR     (DDIM / 4)            // 20 float4 per row

#define NTHREADS 320                  // 10 warps
#define GBLOCKS  888                  // 148 SMs x 6 CTAs: one perfect wave
#define STRIDE   (NTHREADS * GBLOCKS) // 284160, multiple of 20
#define ROWSTEP  (STRIDE / VPR)       // 14208 rows per iteration

// Scratch (no device allocation allowed)
__device__ float        g_pc[GBLOCKS];
__device__ float        g_pl[GBLOCKS];
__device__ unsigned int g_count = 0;
__device__ __align__(16) float g_zero[DDIM];   // zero-initialized row

__device__ __forceinline__ float ex2f(float x) {
    float y; asm("ex2.approx.f32 %0, %1;" : "=f"(y) : "f"(x)); return y;
}
__device__ __forceinline__ float lg2f(float x) {
    float y; asm("lg2.approx.f32 %0, %1;" : "=f"(y) : "f"(x)); return y;
}

// One element: 9 shifted abs-diffs -> softmin partials (round-1 proven form)
__device__ __forceinline__ void elem(float xv,
                                     float u0, float u1, float u2,
                                     float m0, float m1, float m2,
                                     float b0, float b1, float b2,
                                     float& accC, float& accL)
{
    const float C = -46.166241308446828f;   // -32 * log2(e)
    float dc = xv - m1;                     // center (unshifted) diff
    float e0 = ex2f(C * fabsf(xv - u0));
    float e1 = ex2f(C * fabsf(xv - u1));
    float e2 = ex2f(C * fabsf(xv - u2));
    float e3 = ex2f(C * fabsf(xv - m0));
    float e4 = ex2f(C * fabsf(dc));
    float e5 = ex2f(C * fabsf(xv - m2));
    float e6 = ex2f(C * fabsf(xv - b0));
    float e7 = ex2f(C * fabsf(xv - b1));
    float e8 = ex2f(C * fabsf(xv - b2));
    float s = (((e0 + e1) + (e2 + e3)) + ((e4 + e5) + (e6 + e7))) + e8;
    accC += fabsf(dc);
    accL += lg2f(fmaxf(s, 1e-37f));
}

__global__ void __launch_bounds__(NTHREADS, 6)
jitter_fused(const float* __restrict__ in, const float* __restrict__ tg,
             float* __restrict__ out)
{
    const int      tid = threadIdx.x;
    const unsigned t   = blockIdx.x * NTHREADS + tid;

    // Computed ONCE: float4 slot within row is loop-invariant because
    // STRIDE is a multiple of VPR.
    const unsigned jj = t % VPR;
    const unsigned r0 = t / VPR;
    const int  base = jj * 4;
    const bool lv   = (jj > 0);
    const bool rv   = (jj < VPR - 1);

    float accC = 0.0f;
    float accL = 0.0f;

    #pragma unroll 1
    for (int k = 0; k < 10; k++) {
        unsigned row = r0 + (unsigned)k * ROWSTEP;
        if (row >= N_ROWS) break;     // only the 10th iteration can exit
        unsigned i = row & (T_LEN - 1);

        const float* rowM = tg + (size_t)row * DDIM;
        const float* rowU = (i > 0)         ? rowM - DDIM : g_zero;
        const float* rowD = (i < T_LEN - 1) ? rowM + DDIM : g_zero;

        float4 x4 = *reinterpret_cast<const float4*>(in + (size_t)row * DDIM + base);
        float4 u4 = *reinterpret_cast<const float4*>(rowU + base);
        float4 m4 = *reinterpret_cast<const float4*>(rowM + base);
        float4 b4 = *reinterpret_cast<const float4*>(rowD + base);

        float uL = lv ? rowU[base - 1] : 0.0f;
        float mL = lv ? rowM[base - 1] : 0.0f;
        float bL = lv ? rowD[base - 1] : 0.0f;
        float uR = rv ? rowU[base + 4] : 0.0f;
        float mR = rv ? rowM[base + 4] : 0.0f;
        float bR = rv ? rowD[base + 4] : 0.0f;

        elem(x4.x, uL,   u4.x, u4.y,  mL,   m4.x, m4.y,  bL,   b4.x, b4.y, accC, accL);
        elem(x4.y, u4.x, u4.y, u4.z,  m4.x, m4.y, m4.z,  b4.x, b4.y, b4.z, accC, accL);
        elem(x4.z, u4.y, u4.z, u4.w,  m4.y, m4.z, m4.w,  b4.y, b4.z, b4.w, accC, accL);
        elem(x4.w, u4.z, u4.w, uR,    m4.z, m4.w, mR,    b4.z, b4.w, bR,   accC, accL);
    }

    // ---- deterministic in-block reduction: shuffle within warp, smem across
    const int lane = tid & 31;
    const int wid  = tid >> 5;

    #pragma unroll
    for (int off = 16; off > 0; off >>= 1) {
        accC += __shfl_down_sync(0xFFFFFFFFu, accC, off);
        accL += __shfl_down_sync(0xFFFFFFFFu, accL, off);
    }

    __shared__ float shc[NTHREADS / 32];
    __shared__ float shl[NTHREADS / 32];
    if (lane == 0) { shc[wid] = accC; shl[wid] = accL; }
    __syncthreads();

    __shared__ bool isLast;
    if (tid == 0) {
        float sc = shc[0], sl = shl[0];
        #pragma unroll
        for (int w = 1; w < NTHREADS / 32; w++) { sc += shc[w]; sl += shl[w]; }
        g_pc[blockIdx.x] = sc;
        g_pl[blockIdx.x] = sl;
        __threadfence();
        unsigned ticket = atomicAdd(&g_count, 1u);
        isLast = (ticket == GBLOCKS - 1);
    }
    __syncthreads();

    if (isLast) {
        // last block: deterministic final sum over fixed index order
        double dc = 0.0, dl = 0.0;
        for (int k = tid; k < GBLOCKS; k += NTHREADS) {
            dc += (double)__ldcg(&g_pc[k]);
            dl += (double)__ldcg(&g_pl[k]);
        }
        __shared__ double dsc[NTHREADS];
        __shared__ double dsl[NTHREADS];
        dsc[tid] = dc; dsl[tid] = dl;
        __syncthreads();
        // 320 = 64*5: fold 320 -> 64, then power-of-two tree
        if (tid < 64) {
            double c = dsc[tid], l = dsl[tid];
            #pragma unroll
            for (int k = 1; k < 5; k++) { c += dsc[tid + 64 * k]; l += dsl[tid + 64 * k]; }
            dsc[tid] = c; dsl[tid] = l;
        }
        __syncthreads();
        #pragma unroll
        for (int off = 32; off > 0; off >>= 1) {
            if (tid < off) {
                dsc[tid] += dsc[tid + off];
                dsl[tid] += dsl[tid + off];
            }
            __syncthreads();
        }
        if (tid == 0) {
            const double C2d = -0.021660849392498291;  // -ln(2)/32
            double res = (0.5 / (double)N_ELEM) * (dsc[0] + C2d * dsl[0]);
            out[0] = (float)res;
            g_count = 0;   // reset ticket for graph replay
        }
    }
}

extern "C" void kernel_launch(void* const* d_in, const int* in_sizes, int n_in,
                              void* d_out, int out_size)
{
    const float* in = (const float*)d_in[0];
    const float* tg = (const float*)d_in[1];
    float* out = (float*)d_out;

    jitter_fused<<<GBLOCKS, NTHREADS>>>(in, tg, out);
}

// round 8
// speedup vs baseline: 1.2453x; 1.1079x over previous
#include <cuda_runtime.h>

// Problem constants (fixed shapes from setup_inputs)
#define NB      64
#define T_LEN   2048
#define DDIM    80
#define N_ELEM  (NB * T_LEN * DDIM)   // 10,485,760
#define N_VEC   (N_ELEM / 4)          // 2,621,440 float4 elements
#define VPR     (DDIM / 4)            // 20 float4 per row

#define GBLOCKS 1184                  // 8 CTAs per SM on 148 SMs
#define GTHREADS 256

// Scratch (no device allocation allowed)
__device__ float        g_pc[GBLOCKS];
__device__ float        g_pl[GBLOCKS];
__device__ unsigned int g_count = 0;

__device__ __forceinline__ float ex2f(float x) {
    float y; asm("ex2.approx.f32 %0, %1;" : "=f"(y) : "f"(x)); return y;
}
__device__ __forceinline__ float lg2f(float x) {
    float y; asm("lg2.approx.f32 %0, %1;" : "=f"(y) : "f"(x)); return y;
}

__global__ void __launch_bounds__(GTHREADS)
jitter_fused(const float* __restrict__ in, const float* __restrict__ tg,
             float* __restrict__ out)
{
    // ex2 argument scale: -k * log2(e), k = 32
    const float C  = -32.0f * 1.4426950408889634f;

    float accC = 0.0f;   // sum of center abs-diffs
    float accL = 0.0f;   // sum of lg2(softmin-sum)

    for (unsigned g = blockIdx.x * GTHREADS + threadIdx.x; g < N_VEC;
         g += GBLOCKS * GTHREADS)
    {
        unsigned row = g / VPR;          // flattened (b, i) row in [0, 64*2048)
        unsigned jj  = g - row * VPR;    // float4 slot within the row, [0, 20)
        unsigned i   = row & (T_LEN - 1);

        const float* ip = in + (size_t)row * DDIM + jj * 4;
        const float* tp = tg + (size_t)row * DDIM + jj * 4;

        float4 x4 = *reinterpret_cast<const float4*>(ip);
        float x[4] = {x4.x, x4.y, x4.z, x4.w};

        // 3 target rows (i-1, i, i+1) x 6 cols (j-1 .. j+4), zero-padded OOB
        float t[3][6];
        const bool upv = (i > 0);
        const bool dnv = (i < T_LEN - 1);
        const bool lv  = (jj > 0);
        const bool rv  = (jj < VPR - 1);

        const float* rows[3] = {tp - DDIM, tp, tp + DDIM};
        const bool   rok[3]  = {upv, true, dnv};

        #pragma unroll
        for (int r = 0; r < 3; r++) {
            if (rok[r]) {
                float4 t4 = *reinterpret_cast<const float4*>(rows[r]);
                t[r][1] = t4.x; t[r][2] = t4.y; t[r][3] = t4.z; t[r][4] = t4.w;
                t[r][0] = lv ? rows[r][-1] : 0.0f;
                t[r][5] = rv ? rows[r][4]  : 0.0f;
            } else {
                #pragma unroll
                for (int c = 0; c < 6; c++) t[r][c] = 0.0f;
            }
        }

        #pragma unroll
        for (int e = 0; e < 4; e++) {
            float xv = x[e];
            float s = 0.0f;
            #pragma unroll
            for (int r = 0; r < 3; r++) {
                #pragma unroll
                for (int c = 0; c < 3; c++) {
                    float d = fabsf(xv - t[r][e + c]);
                    s += ex2f(C * d);
                }
            }
            float center = fabsf(xv - t[1][e + 1]);   // (dy=0, dx=0)
            accC += center;
            accL += lg2f(fmaxf(s, 1e-37f));
        }
    }

    // ---- deterministic block tree reduction (as in R1) ----
    __shared__ float shc[GTHREADS];
    __shared__ float shl[GTHREADS];
    shc[threadIdx.x] = accC;
    shl[threadIdx.x] = accL;
    __syncthreads();
    #pragma unroll
    for (int off = GTHREADS / 2; off > 0; off >>= 1) {
        if (threadIdx.x < off) {
            shc[threadIdx.x] += shc[threadIdx.x + off];
            shl[threadIdx.x] += shl[threadIdx.x + off];
        }
        __syncthreads();
    }

    // ---- fused final reduction via ticket (last block) ----
    __shared__ bool isLast;
    if (threadIdx.x == 0) {
        g_pc[blockIdx.x] = shc[0];
        g_pl[blockIdx.x] = shl[0];
        __threadfence();
        unsigned ticket = atomicAdd(&g_count, 1u);
        isLast = (ticket == GBLOCKS - 1);
    }
    __syncthreads();

    if (isLast) {
        __shared__ double dsc[GTHREADS];
        __shared__ double dsl[GTHREADS];
        double dc = 0.0, dl = 0.0;
        for (int k = threadIdx.x; k < GBLOCKS; k += GTHREADS) {
            dc += (double)__ldcg(&g_pc[k]);
            dl += (double)__ldcg(&g_pl[k]);
        }
        dsc[threadIdx.x] = dc;
        dsl[threadIdx.x] = dl;
        __syncthreads();
        #pragma unroll
        for (int off = GTHREADS / 2; off > 0; off >>= 1) {
            if (threadIdx.x < off) {
                dsc[threadIdx.x] += dsc[threadIdx.x + off];
                dsl[threadIdx.x] += dsl[threadIdx.x + off];
            }
            __syncthreads();
        }
        if (threadIdx.x == 0) {
            const double C2d = -0.021660849392498291;  // -ln(2)/32
            double res = (0.5 / (double)N_ELEM) * (dsc[0] + C2d * dsl[0]);
            out[0] = (float)res;
            g_count = 0;   // reset ticket for graph replay
        }
    }
}

extern "C" void kernel_launch(void* const* d_in, const int* in_sizes, int n_in,
                              void* d_out, int out_size)
{
    const float* in = (const float*)d_in[0];
    const float* tg = (const float*)d_in[1];
    float* out = (float*)d_out;

    jitter_fused<<<GBLOCKS, GTHREADS>>>(in, tg, out);
}